// round 9
// baseline (speedup 1.0000x reference)
#include <cuda_runtime.h>
#include <cstdint>
#include <cstddef>

// ---------------------------------------------------------------- constants
#define NB   4
#define NS_N 10000
#define NT_N 10000
#define NE   160000
#define NK   16
#define ND   128
#define M_NODES 40000
#define TILES_NODE 313
#define TILES_EDGE 5000
#define TILES_PER_BATCH 1250

// SMEM floats: A0[128*132], A1[128*132], BT[128*132], C[32*132]
#define LDT 132
#define A1_OFF 16896
#define BT_OFF 33792
#define C_OFF  50688
#define SMEM_FLOATS (C_OFF + 32 * LDT)     // 54912
#define SMEM_BYTES (SMEM_FLOATS * 4)       // 219648

#define GRID_P 148

// ---------------------------------------------------------------- scratch
__device__ float g_Ps[(size_t)NB * NS_N * ND];
__device__ float g_Pt[(size_t)NB * NT_N * ND];
__device__ float g_dbond[(size_t)NB * NE * ND];
__device__ float g_bred[(size_t)NB * NT_N * ND];
__device__ float g_tmp[(size_t)NB * NT_N * ND];

// ---------------------------------------------------------------- helpers
__device__ __forceinline__ unsigned f2tf(float f) {
    unsigned r; asm("cvt.rna.tf32.f32 %0, %1;" : "=r"(r) : "f"(f)); return r;
}
__device__ __forceinline__ void mma8(float c[4], const unsigned a[4], const unsigned b0,
                                     const unsigned b1) {
    asm volatile(
        "mma.sync.aligned.m16n8k8.row.col.f32.tf32.tf32.f32 "
        "{%0,%1,%2,%3},{%4,%5,%6,%7},{%8,%9},{%0,%1,%2,%3};"
        : "+f"(c[0]), "+f"(c[1]), "+f"(c[2]), "+f"(c[3])
        : "r"(a[0]), "r"(a[1]), "r"(a[2]), "r"(a[3]), "r"(b0), "r"(b1));
}
__device__ __forceinline__ void ldsm4(unsigned r[4], uint32_t addr) {
    asm volatile("ldmatrix.sync.aligned.m8n8.x4.shared.b16 {%0,%1,%2,%3}, [%4];"
                 : "=r"(r[0]), "=r"(r[1]), "=r"(r[2]), "=r"(r[3]) : "r"(addr));
}
__device__ __forceinline__ float silu_f(float x) { return x / (1.f + __expf(-x)); }

__device__ __forceinline__ void prefetch_A(float* Adst, const float* __restrict__ Ag,
                                           size_t row0, size_t M, int tid) {
    uint32_t dst0 = (uint32_t)__cvta_generic_to_shared(Adst);
    #pragma unroll
    for (int i = 0; i < 16; ++i) {
        int t = tid + i * 256;
        int r = t >> 5, c4 = (t & 31) << 2;
        size_t rr = row0 + (size_t)r;
        if (rr >= M) rr = M - 1;
        uint32_t d = dst0 + (uint32_t)(r * LDT + c4) * 4u;
        const float* s = Ag + rr * ND + c4;
        asm volatile("cp.async.cg.shared.global [%0], [%1], 16;" :: "r"(d), "l"(s));
    }
}
__device__ __forceinline__ void cpa_commit() { asm volatile("cp.async.commit_group;" ::: "memory"); }
__device__ __forceinline__ void cpa_wait0()  { asm volatile("cp.async.wait_group 0;"  ::: "memory"); }

// BT[n][k] = tf32(W[k][n])   (staged once per persistent CTA)
__device__ __forceinline__ void stage_BT(float* BT, const float* __restrict__ W, int tid) {
    #pragma unroll
    for (int i = 0; i < 16; ++i) {
        int t = tid + i * 256;
        int k = t >> 5, c4 = (t & 31) << 2;
        float4 v = *(const float4*)(W + k * ND + c4);
        BT[(c4 + 0) * LDT + k] = __uint_as_float(f2tf(v.x));
        BT[(c4 + 1) * LDT + k] = __uint_as_float(f2tf(v.y));
        BT[(c4 + 2) * LDT + k] = __uint_as_float(f2tf(v.z));
        BT[(c4 + 3) * LDT + k] = __uint_as_float(f2tf(v.w));
    }
}

// 128x128x128 tile GEMM: 8 warps (4m x 2n), warp tile 32x64, ldmatrix-fed, frag dbl-buffer
__device__ __forceinline__ void tile_gemm(uint32_t a0b, uint32_t a1b, const uint32_t bb[4],
                                          float c[2][8][4]) {
    unsigned a[2][2][4];
    unsigned bt[2][4][4];
#define LOADK(s, kb) do { \
    ldsm4(a[s][0], a0b + (kb)); \
    ldsm4(a[s][1], a1b + (kb)); \
    ldsm4(bt[s][0], bb[0] + (kb)); \
    ldsm4(bt[s][1], bb[1] + (kb)); \
    ldsm4(bt[s][2], bb[2] + (kb)); \
    ldsm4(bt[s][3], bb[3] + (kb)); } while (0)
    LOADK(0, 0);
    #pragma unroll
    for (int kk = 0; kk < 16; ++kk) {
        int s = kk & 1;
        if (kk < 15) {
            uint32_t kb = (uint32_t)(kk + 1) * 32u;
            if (s == 0) LOADK(1, kb); else LOADK(0, kb);
        }
        #pragma unroll
        for (int i = 0; i < 2; ++i)
            #pragma unroll
            for (int j = 0; j < 8; ++j)
                mma8(c[i][j], a[s][i], bt[s][j >> 1][j & 1], bt[s][j >> 1][2 + (j & 1)]);
    }
#undef LOADK
}

// ---------------------------------------------------------------- fused persistent GEMM
// MODE 0: out_main = A @ W
// MODE 1: edge — x=silu(acc+Ps[so]+Pt[to]); y=LN(x); g_dbond=y; out_main=bond+y
// MODE 2: tgt  — x=silu(acc+extra);         y=LN(x); out_main=tgt+y
template <int MODE>
__global__ __launch_bounds__(256) void gemm_fused(const float* __restrict__ Ag,
                                                  const float* __restrict__ Wg,
                                                  const float* __restrict__ extra,
                                                  const float* __restrict__ lng,
                                                  const float* __restrict__ lnb,
                                                  const int* __restrict__ so,
                                                  const int* __restrict__ to,
                                                  float* __restrict__ out_main,
                                                  int ntiles, size_t M) {
    extern __shared__ float sm[];
    float* BT  = sm + BT_OFF;
    float* Csh = sm + C_OFF;
    int tid = threadIdx.x, lane = tid & 31, wid = tid >> 5;
    int wm = wid & 3, wn = wid >> 2;
    int lr = lane >> 2, lc = lane & 3;
    int cc = lane << 2;

    stage_BT(BT, Wg, tid);

    uint32_t smb = (uint32_t)__cvta_generic_to_shared(sm);
    int mrow = ((lane >> 3) & 1) * 8 + (lane & 7);
    int kcol = (lane >> 4) << 2;
    uint32_t aoff0 = (uint32_t)((wm * 32 + mrow) * LDT + kcol) * 4u;
    uint32_t aoff1 = (uint32_t)((wm * 32 + 16 + mrow) * LDT + kcol) * 4u;
    uint32_t bb[4];
    #pragma unroll
    for (int p = 0; p < 4; ++p)
        bb[p] = smb + (uint32_t)(BT_OFF + (wn * 64 + p * 16 + mrow) * LDT + kcol) * 4u;

    float4 gg = make_float4(0.f, 0.f, 0.f, 0.f), bbv = gg;
    if (MODE != 0) {
        gg  = *(const float4*)(lng + cc);
        bbv = *(const float4*)(lnb + cc);
    }

    if (blockIdx.x < (unsigned)ntiles)
        prefetch_A(sm, Ag, (size_t)blockIdx.x * 128, M, tid);
    cpa_commit();

    int buf = 0;
    for (int t = blockIdx.x; t < ntiles; t += gridDim.x, buf ^= 1) {
        cpa_wait0();
        __syncthreads();
        int tn = t + gridDim.x;
        if (tn < ntiles)
            prefetch_A(sm + (buf ^ 1) * A1_OFF, Ag, (size_t)tn * 128, M, tid);
        cpa_commit();

        const float* Ash = sm + buf * A1_OFF;
        uint32_t abase = smb + (uint32_t)(buf * A1_OFF) * 4u;

        float c[2][8][4];
        #pragma unroll
        for (int i = 0; i < 2; ++i)
            #pragma unroll
            for (int j = 0; j < 8; ++j)
                c[i][j][0] = c[i][j][1] = c[i][j][2] = c[i][j][3] = 0.f;

        tile_gemm(abase + aoff0, abase + aoff1, bb, c);

        size_t row0 = (size_t)t * 128;
        int b = 0, el0 = 0;
        const float* PsB = nullptr;
        const float* PtB = nullptr;
        if (MODE == 1) {
            b = t / TILES_PER_BATCH;
            el0 = (t - b * TILES_PER_BATCH) * 128;
            PsB = g_Ps + (size_t)b * NS_N * ND;
            PtB = g_Pt + (size_t)b * NT_N * ND;
        }

        // 4 passes of 32 rows through the C staging buffer
        #pragma unroll 1
        for (int p = 0; p < 4; ++p) {
            __syncthreads();
            if (wm == p) {
                #pragma unroll
                for (int i = 0; i < 2; ++i)
                    #pragma unroll
                    for (int j = 0; j < 8; ++j) {
                        int rl = i * 16 + lr;
                        int col = wn * 64 + j * 8 + lc * 2;
                        *(float2*)(Csh + rl * LDT + col)       = make_float2(c[i][j][0], c[i][j][1]);
                        *(float2*)(Csh + (rl + 8) * LDT + col) = make_float2(c[i][j][2], c[i][j][3]);
                    }
            }
            __syncthreads();

            #pragma unroll 1
            for (int rr = 0; rr < 4; ++rr) {
                int rl = wid * 4 + rr;          // 0..31 within pass
                int r  = p * 32 + rl;           // 0..127 within tile
                size_t gr = row0 + (size_t)r;
                float4 v = *(const float4*)(Csh + rl * LDT + cc);

                if (MODE == 0) {
                    if (gr < M)
                        *(float4*)(out_main + gr * ND + cc) = v;
                    continue;
                }

                float x0, x1, x2, x3;
                if (MODE == 1) {
                    int el = el0 + r;
                    int si = __ldg(so + el);
                    int ti = __ldg(to + el);
                    float4 ps = *(const float4*)(PsB + (size_t)si * ND + cc);
                    float4 pt = *(const float4*)(PtB + (size_t)ti * ND + cc);
                    x0 = silu_f(v.x + ps.x + pt.x);
                    x1 = silu_f(v.y + ps.y + pt.y);
                    x2 = silu_f(v.z + ps.z + pt.z);
                    x3 = silu_f(v.w + ps.w + pt.w);
                } else {
                    size_t grc = gr < M ? gr : (M - 1);
                    float4 ex = *(const float4*)(extra + grc * ND + cc);
                    x0 = silu_f(v.x + ex.x);
                    x1 = silu_f(v.y + ex.y);
                    x2 = silu_f(v.z + ex.z);
                    x3 = silu_f(v.w + ex.w);
                }
                float s = x0 + x1 + x2 + x3;
                float q = x0 * x0 + x1 * x1 + x2 * x2 + x3 * x3;
                #pragma unroll
                for (int o = 16; o > 0; o >>= 1) {
                    s += __shfl_xor_sync(0xffffffffu, s, o);
                    q += __shfl_xor_sync(0xffffffffu, q, o);
                }
                float mean = s * (1.f / ND);
                float var  = q * (1.f / ND) - mean * mean;
                float rstd = rsqrtf(var + 1e-5f);
                float y0 = (x0 - mean) * rstd * gg.x + bbv.x;
                float y1 = (x1 - mean) * rstd * gg.y + bbv.y;
                float y2 = (x2 - mean) * rstd * gg.z + bbv.z;
                float y3 = (x3 - mean) * rstd * gg.w + bbv.w;
                float4 av = *(const float4*)(Ash + r * LDT + cc);   // exact fp32 A (bond/tgt)
                if (MODE == 1) {
                    size_t off = gr * ND + cc;
                    *(float4*)(g_dbond + off) = make_float4(y0, y1, y2, y3);
                    *(float4*)(out_main + off) = make_float4(av.x + y0, av.y + y1, av.z + y2, av.w + y3);
                } else {
                    if (gr < M)
                        *(float4*)(out_main + gr * ND + cc) =
                            make_float4(av.x + y0, av.y + y1, av.z + y2, av.w + y3);
                }
            }
        }
        __syncthreads();
    }
}

// ---------------------------------------------------------------- gather
__global__ __launch_bounds__(128) void gather_kernel(const int* __restrict__ edge_order,
                                                     const float* __restrict__ coef) {
    int bn = blockIdx.x;                 // 0 .. B*NT-1
    int b = bn / NT_N, nt = bn - b * NT_N;
    __shared__ int   eo[NK];
    __shared__ float cf[NK];
    if (threadIdx.x < NK) {
        eo[threadIdx.x] = edge_order[nt * NK + threadIdx.x];
        cf[threadIdx.x] = coef[nt * NK + threadIdx.x];
    }
    __syncthreads();
    int d = threadIdx.x;
    const float* base = g_dbond + (size_t)b * NE * ND;
    float acc = 0.f;
    #pragma unroll
    for (int k = 0; k < NK; ++k)
        acc += cf[k] * __ldg(base + (size_t)eo[k] * ND + d);
    g_bred[(size_t)bn * ND + d] = acc * (1.f / NK);
}

// ---------------------------------------------------------------- launch
extern "C" void kernel_launch(void* const* d_in, const int* in_sizes, int n_in,
                              void* d_out, int out_size) {
    const float* bond = (const float*)d_in[0];
    const float* src  = (const float*)d_in[1];
    const float* tgt  = (const float*)d_in[2];
    const float* Ws2e = (const float*)d_in[3];
    const float* Wt2e = (const float*)d_in[4];
    const float* We2e = (const float*)d_in[5];
    const float* ln1g = (const float*)d_in[6];
    const float* ln1b = (const float*)d_in[7];
    const float* We2t = (const float*)d_in[8];
    const float* Wt2t = (const float*)d_in[9];
    const float* ln2g = (const float*)d_in[10];
    const float* ln2b = (const float*)d_in[11];
    const float* coef = (const float*)d_in[12];
    const int* so = (const int*)d_in[13];
    const int* to = (const int*)d_in[14];
    const int* eo = (const int*)d_in[15];

    float* out0 = (float*)d_out;                     // [B,E,D]
    float* out1 = out0 + (size_t)NB * NE * ND;       // [B,NS,D]
    float* out2 = out1 + (size_t)NB * NS_N * ND;     // [B,NT,D]

    static float* s_Ps = nullptr;
    static float* s_Pt = nullptr;
    static float* s_bred = nullptr;
    static float* s_tmp = nullptr;
    if (!s_Ps) {
        cudaGetSymbolAddress((void**)&s_Ps, g_Ps);
        cudaGetSymbolAddress((void**)&s_Pt, g_Pt);
        cudaGetSymbolAddress((void**)&s_bred, g_bred);
        cudaGetSymbolAddress((void**)&s_tmp, g_tmp);
    }

    cudaFuncSetAttribute(gemm_fused<0>, cudaFuncAttributeMaxDynamicSharedMemorySize, SMEM_BYTES);
    cudaFuncSetAttribute(gemm_fused<1>, cudaFuncAttributeMaxDynamicSharedMemorySize, SMEM_BYTES);
    cudaFuncSetAttribute(gemm_fused<2>, cudaFuncAttributeMaxDynamicSharedMemorySize, SMEM_BYTES);

    // out1 = src
    cudaMemcpyAsync(out1, src, (size_t)NB * NS_N * ND * sizeof(float),
                    cudaMemcpyDeviceToDevice);

    // P_s = src @ W_s2e ; P_t = tgt @ W_t2e
    gemm_fused<0><<<GRID_P, 256, SMEM_BYTES>>>(src, Ws2e, nullptr, nullptr, nullptr,
                                               nullptr, nullptr, s_Ps, TILES_NODE, (size_t)M_NODES);
    gemm_fused<0><<<GRID_P, 256, SMEM_BYTES>>>(tgt, Wt2e, nullptr, nullptr, nullptr,
                                               nullptr, nullptr, s_Pt, TILES_NODE, (size_t)M_NODES);
    // edge block
    gemm_fused<1><<<GRID_P, 256, SMEM_BYTES>>>(bond, We2e, nullptr, ln1g, ln1b,
                                               so, to, out0, TILES_EDGE, (size_t)NB * NE);
    // bond -> node reduce
    gather_kernel<<<NB * NT_N, 128>>>(eo, coef);
    // g_tmp = bred @ We2t
    gemm_fused<0><<<GRID_P, 256, SMEM_BYTES>>>(s_bred, We2t, nullptr, nullptr, nullptr,
                                               nullptr, nullptr, s_tmp, TILES_NODE, (size_t)M_NODES);
    // out2 = tgt + LN(silu(tgt@Wt2t + g_tmp))
    gemm_fused<2><<<GRID_P, 256, SMEM_BYTES>>>(tgt, Wt2t, s_tmp, ln2g, ln2b,
                                               nullptr, nullptr, out2, TILES_NODE, (size_t)M_NODES);
}

// round 11
// speedup vs baseline: 1.5050x; 1.5050x over previous
#include <cuda_runtime.h>
#include <cstdint>
#include <cstddef>

// ---------------------------------------------------------------- constants
#define NB   4
#define NS_N 10000
#define NT_N 10000
#define NE   160000
#define NK   16
#define ND   128
#define M_NODES 40000
#define TILES_NODE 313
#define TILES_EDGE 5000
#define TILES_PER_BATCH 1250

#define NTHR 512

// SMEM floats: slot0[128*132], slot1[128*132], slot2[128*132], C[32*132]
// proj/edge: A0=slot0, A1=slot1, BT=slot2
// tgt_fused: A=slot0, BT1=slot1, BT2=slot2
#define LDT 132
#define SLOT 16896
#define C_OFF (3 * SLOT)                   // 50688
#define SMEM_FLOATS (C_OFF + 32 * LDT)     // 54912
#define SMEM_BYTES (SMEM_FLOATS * 4)       // 219648

// ---------------------------------------------------------------- scratch
__device__ float g_Ps[(size_t)NB * NS_N * ND];
__device__ float g_Pt[(size_t)NB * NT_N * ND];
__device__ float g_dbond[(size_t)NB * NE * ND];
__device__ float g_bred[(size_t)NB * NT_N * ND];

// ---------------------------------------------------------------- helpers
__device__ __forceinline__ unsigned f2tf(float f) {
    unsigned r; asm("cvt.rna.tf32.f32 %0, %1;" : "=r"(r) : "f"(f)); return r;
}
__device__ __forceinline__ void mma8(float c[4], const unsigned a[4], const unsigned b0,
                                     const unsigned b1) {
    asm volatile(
        "mma.sync.aligned.m16n8k8.row.col.f32.tf32.tf32.f32 "
        "{%0,%1,%2,%3},{%4,%5,%6,%7},{%8,%9},{%0,%1,%2,%3};"
        : "+f"(c[0]), "+f"(c[1]), "+f"(c[2]), "+f"(c[3])
        : "r"(a[0]), "r"(a[1]), "r"(a[2]), "r"(a[3]), "r"(b0), "r"(b1));
}
__device__ __forceinline__ void ldsm4(unsigned r[4], uint32_t addr) {
    asm volatile("ldmatrix.sync.aligned.m8n8.x4.shared.b16 {%0,%1,%2,%3}, [%4];"
                 : "=r"(r[0]), "=r"(r[1]), "=r"(r[2]), "=r"(r[3]) : "r"(addr));
}
__device__ __forceinline__ float silu_f(float x) { return x / (1.f + __expf(-x)); }

__device__ __forceinline__ void prefetch_A(float* Adst, const float* __restrict__ Ag,
                                           size_t row0, size_t M, int tid) {
    uint32_t dst0 = (uint32_t)__cvta_generic_to_shared(Adst);
    #pragma unroll
    for (int i = 0; i < 8; ++i) {
        int t = tid + i * NTHR;
        int r = t >> 5, c4 = (t & 31) << 2;
        size_t rr = row0 + (size_t)r;
        if (rr >= M) rr = M - 1;
        uint32_t d = dst0 + (uint32_t)(r * LDT + c4) * 4u;
        const float* s = Ag + rr * ND + c4;
        asm volatile("cp.async.cg.shared.global [%0], [%1], 16;" :: "r"(d), "l"(s));
    }
}
__device__ __forceinline__ void cpa_commit() { asm volatile("cp.async.commit_group;" ::: "memory"); }
__device__ __forceinline__ void cpa_wait0()  { asm volatile("cp.async.wait_group 0;"  ::: "memory"); }

// BT[n][k] = tf32(W[k][n])
__device__ __forceinline__ void stage_BT(float* BT, const float* __restrict__ W, int tid) {
    #pragma unroll
    for (int i = 0; i < 8; ++i) {
        int t = tid + i * NTHR;
        int k = t >> 5, c4 = (t & 31) << 2;
        float4 v = *(const float4*)(W + k * ND + c4);
        BT[(c4 + 0) * LDT + k] = __uint_as_float(f2tf(v.x));
        BT[(c4 + 1) * LDT + k] = __uint_as_float(f2tf(v.y));
        BT[(c4 + 2) * LDT + k] = __uint_as_float(f2tf(v.z));
        BT[(c4 + 3) * LDT + k] = __uint_as_float(f2tf(v.w));
    }
}

// 128x128x128 tile GEMM: 16 warps (4m x 4n), warp tile 32x32, ldmatrix-fed, dbl-buffered frags
__device__ __forceinline__ void tile_gemm(uint32_t a0b, uint32_t a1b, const uint32_t bb[2],
                                          float c[2][4][4]) {
    unsigned a[2][2][4];
    unsigned bt[2][2][4];
#define LOADK(s, kb) do { \
    ldsm4(a[s][0], a0b + (kb)); \
    ldsm4(a[s][1], a1b + (kb)); \
    ldsm4(bt[s][0], bb[0] + (kb)); \
    ldsm4(bt[s][1], bb[1] + (kb)); } while (0)
    LOADK(0, 0);
    #pragma unroll
    for (int kk = 0; kk < 16; ++kk) {
        int s = kk & 1;
        if (kk < 15) {
            uint32_t kb = (uint32_t)(kk + 1) * 32u;
            if (s == 0) LOADK(1, kb); else LOADK(0, kb);
        }
        #pragma unroll
        for (int i = 0; i < 2; ++i)
            #pragma unroll
            for (int j = 0; j < 4; ++j)
                mma8(c[i][j], a[s][i], bt[s][j >> 1][j & 1], bt[s][j >> 1][2 + (j & 1)]);
    }
#undef LOADK
}

__device__ __forceinline__ void zero_c(float c[2][4][4]) {
    #pragma unroll
    for (int i = 0; i < 2; ++i)
        #pragma unroll
        for (int j = 0; j < 4; ++j)
            c[i][j][0] = c[i][j][1] = c[i][j][2] = c[i][j][3] = 0.f;
}

// stage one 32-row pass of C (warps with wm==p write)
__device__ __forceinline__ void stage_pass(float* Csh, float c[2][4][4], int p,
                                           int wm, int wn, int lr, int lc) {
    if (wm == p) {
        #pragma unroll
        for (int i = 0; i < 2; ++i)
            #pragma unroll
            for (int j = 0; j < 4; ++j) {
                int rl = i * 16 + lr;
                int col = wn * 32 + j * 8 + lc * 2;
                *(float2*)(Csh + rl * LDT + col)       = make_float2(c[i][j][0], c[i][j][1]);
                *(float2*)(Csh + (rl + 8) * LDT + col) = make_float2(c[i][j][2], c[i][j][3]);
            }
    }
}

// ---------------------------------------------------------------- K1: projections (persistent)
// y==0: g_Ps = src @ Ws2e, and out1 = src (exact copy from resident tile)
// y==1: g_Pt = tgt @ Wt2e
__global__ __launch_bounds__(NTHR) void proj_kernel(const float* __restrict__ src,
                                                    const float* __restrict__ tgt,
                                                    const float* __restrict__ Ws,
                                                    const float* __restrict__ Wt,
                                                    float* __restrict__ out1) {
    extern __shared__ float sm[];
    float* BT  = sm + 2 * SLOT;
    float* Csh = sm + C_OFF;
    int tid = threadIdx.x, lane = tid & 31, wid = tid >> 5;
    int wm = wid & 3, wn = wid >> 2;
    int lr = lane >> 2, lc = lane & 3;
    int cc = lane << 2;

    const float* Ag = blockIdx.y ? tgt : src;
    const float* Wg = blockIdx.y ? Wt : Ws;
    float* O = blockIdx.y ? g_Pt : g_Ps;
    float* copy_out = blockIdx.y ? nullptr : out1;

    stage_BT(BT, Wg, tid);

    uint32_t smb = (uint32_t)__cvta_generic_to_shared(sm);
    int mrow = ((lane >> 3) & 1) * 8 + (lane & 7);
    int kcol = (lane >> 4) << 2;
    uint32_t aoff0 = (uint32_t)((wm * 32 + mrow) * LDT + kcol) * 4u;
    uint32_t aoff1 = (uint32_t)((wm * 32 + 16 + mrow) * LDT + kcol) * 4u;
    uint32_t bb[2];
    #pragma unroll
    for (int p = 0; p < 2; ++p)
        bb[p] = smb + (uint32_t)(2 * SLOT + (wn * 32 + p * 16 + mrow) * LDT + kcol) * 4u;

    prefetch_A(sm, Ag, (size_t)blockIdx.x * 128, (size_t)M_NODES, tid);
    cpa_commit();

    int buf = 0;
    for (int t = blockIdx.x; t < TILES_NODE; t += gridDim.x, buf ^= 1) {
        cpa_wait0();
        __syncthreads();
        int tn = t + gridDim.x;
        if (tn < TILES_NODE)
            prefetch_A(sm + (buf ^ 1) * SLOT, Ag, (size_t)tn * 128, (size_t)M_NODES, tid);
        cpa_commit();

        const float* Ash = sm + buf * SLOT;
        uint32_t abase = smb + (uint32_t)(buf * SLOT) * 4u;
        size_t row0 = (size_t)t * 128;

        float c[2][4][4];
        zero_c(c);
        tile_gemm(abase + aoff0, abase + aoff1, bb, c);

        // exact src copy to out1 (8 rows per warp)
        if (copy_out) {
            #pragma unroll
            for (int rr = 0; rr < 8; ++rr) {
                int r = wid * 8 + rr;
                size_t gr = row0 + (size_t)r;
                if (gr < (size_t)M_NODES)
                    *(float4*)(copy_out + gr * ND + cc) = *(const float4*)(Ash + r * LDT + cc);
            }
        }

        #pragma unroll 1
        for (int p = 0; p < 4; ++p) {
            __syncthreads();
            stage_pass(Csh, c, p, wm, wn, lr, lc);
            __syncthreads();
            #pragma unroll
            for (int rr = 0; rr < 2; ++rr) {
                int rl = wid * 2 + rr;
                size_t gr = row0 + (size_t)(p * 32 + rl);
                if (gr < (size_t)M_NODES)
                    *(float4*)(O + gr * ND + cc) = *(const float4*)(Csh + rl * LDT + cc);
            }
        }
        __syncthreads();
    }
}

// ---------------------------------------------------------------- K2: edge block (persistent)
__global__ __launch_bounds__(NTHR) void edge_kernel(const float* __restrict__ bond,
                                                    const float* __restrict__ We2e,
                                                    const float* __restrict__ lng,
                                                    const float* __restrict__ lnb,
                                                    const int* __restrict__ so,
                                                    const int* __restrict__ to,
                                                    float* __restrict__ out0) {
    extern __shared__ float sm[];
    float* BT  = sm + 2 * SLOT;
    float* Csh = sm + C_OFF;
    int tid = threadIdx.x, lane = tid & 31, wid = tid >> 5;
    int wm = wid & 3, wn = wid >> 2;
    int lr = lane >> 2, lc = lane & 3;
    int cc = lane << 2;

    stage_BT(BT, We2e, tid);

    uint32_t smb = (uint32_t)__cvta_generic_to_shared(sm);
    int mrow = ((lane >> 3) & 1) * 8 + (lane & 7);
    int kcol = (lane >> 4) << 2;
    uint32_t aoff0 = (uint32_t)((wm * 32 + mrow) * LDT + kcol) * 4u;
    uint32_t aoff1 = (uint32_t)((wm * 32 + 16 + mrow) * LDT + kcol) * 4u;
    uint32_t bb[2];
    #pragma unroll
    for (int p = 0; p < 2; ++p)
        bb[p] = smb + (uint32_t)(2 * SLOT + (wn * 32 + p * 16 + mrow) * LDT + kcol) * 4u;

    float4 gg  = *(const float4*)(lng + cc);
    float4 bbv = *(const float4*)(lnb + cc);

    prefetch_A(sm, bond, (size_t)blockIdx.x * 128, (size_t)NB * NE, tid);
    cpa_commit();

    int buf = 0;
    for (int t = blockIdx.x; t < TILES_EDGE; t += gridDim.x, buf ^= 1) {
        cpa_wait0();
        __syncthreads();
        int tn = t + gridDim.x;
        if (tn < TILES_EDGE)
            prefetch_A(sm + (buf ^ 1) * SLOT, bond, (size_t)tn * 128, (size_t)NB * NE, tid);
        cpa_commit();

        const float* Ash = sm + buf * SLOT;
        uint32_t abase = smb + (uint32_t)(buf * SLOT) * 4u;
        size_t row0 = (size_t)t * 128;

        float c[2][4][4];
        zero_c(c);
        tile_gemm(abase + aoff0, abase + aoff1, bb, c);

        int b = t / TILES_PER_BATCH;
        int el0 = (t - b * TILES_PER_BATCH) * 128;
        const float* PsB = g_Ps + (size_t)b * NS_N * ND;
        const float* PtB = g_Pt + (size_t)b * NT_N * ND;

        #pragma unroll 1
        for (int p = 0; p < 4; ++p) {
            __syncthreads();
            stage_pass(Csh, c, p, wm, wn, lr, lc);
            __syncthreads();
            #pragma unroll
            for (int rr = 0; rr < 2; ++rr) {
                int rl = wid * 2 + rr;
                int r = p * 32 + rl;
                int el = el0 + r;
                int si = __ldg(so + el);
                int ti = __ldg(to + el);
                float4 v  = *(const float4*)(Csh + rl * LDT + cc);
                float4 ps = *(const float4*)(PsB + (size_t)si * ND + cc);
                float4 pt = *(const float4*)(PtB + (size_t)ti * ND + cc);
                float x0 = silu_f(v.x + ps.x + pt.x);
                float x1 = silu_f(v.y + ps.y + pt.y);
                float x2 = silu_f(v.z + ps.z + pt.z);
                float x3 = silu_f(v.w + ps.w + pt.w);
                float s = x0 + x1 + x2 + x3;
                float q = x0 * x0 + x1 * x1 + x2 * x2 + x3 * x3;
                #pragma unroll
                for (int o = 16; o > 0; o >>= 1) {
                    s += __shfl_xor_sync(0xffffffffu, s, o);
                    q += __shfl_xor_sync(0xffffffffu, q, o);
                }
                float mean = s * (1.f / ND);
                float var  = q * (1.f / ND) - mean * mean;
                float rstd = rsqrtf(var + 1e-5f);
                float y0 = (x0 - mean) * rstd * gg.x + bbv.x;
                float y1 = (x1 - mean) * rstd * gg.y + bbv.y;
                float y2 = (x2 - mean) * rstd * gg.z + bbv.z;
                float y3 = (x3 - mean) * rstd * gg.w + bbv.w;
                size_t off = (row0 + (size_t)r) * ND + cc;
                float4 av = *(const float4*)(Ash + r * LDT + cc);   // exact fp32 bond
                *(float4*)(g_dbond + off) = make_float4(y0, y1, y2, y3);
                *(float4*)(out0 + off) = make_float4(av.x + y0, av.y + y1, av.z + y2, av.w + y3);
            }
        }
        __syncthreads();
    }
}

// ---------------------------------------------------------------- K3: gather
__global__ __launch_bounds__(128) void gather_kernel(const int* __restrict__ edge_order,
                                                     const float* __restrict__ coef) {
    int bn = blockIdx.x;                 // 0 .. B*NT-1
    int b = bn / NT_N, nt = bn - b * NT_N;
    __shared__ int   eo[NK];
    __shared__ float cf[NK];
    if (threadIdx.x < NK) {
        eo[threadIdx.x] = edge_order[nt * NK + threadIdx.x];
        cf[threadIdx.x] = coef[nt * NK + threadIdx.x];
    }
    __syncthreads();
    int d = threadIdx.x;
    const float* base = g_dbond + (size_t)b * NE * ND;
    float acc = 0.f;
    #pragma unroll
    for (int k = 0; k < NK; ++k)
        acc += cf[k] * __ldg(base + (size_t)eo[k] * ND + d);
    g_bred[(size_t)bn * ND + d] = acc * (1.f / NK);
}

// ---------------------------------------------------------------- K4: fused tgt update
// out2 = tgt + LN(silu(bred@We2t + tgt@Wt2t))   (both weights SMEM-resident)
__global__ __launch_bounds__(NTHR) void tgt_fused(const float* __restrict__ tgt,
                                                  const float* __restrict__ We2t,
                                                  const float* __restrict__ Wt2t,
                                                  const float* __restrict__ lng,
                                                  const float* __restrict__ lnb,
                                                  float* __restrict__ out2) {
    extern __shared__ float sm[];
    float* BT1 = sm + SLOT;
    float* BT2 = sm + 2 * SLOT;
    float* Csh = sm + C_OFF;
    int tid = threadIdx.x, lane = tid & 31, wid = tid >> 5;
    int wm = wid & 3, wn = wid >> 2;
    int lr = lane >> 2, lc = lane & 3;
    int cc = lane << 2;

    stage_BT(BT1, We2t, tid);
    stage_BT(BT2, Wt2t, tid);

    uint32_t smb = (uint32_t)__cvta_generic_to_shared(sm);
    int mrow = ((lane >> 3) & 1) * 8 + (lane & 7);
    int kcol = (lane >> 4) << 2;
    uint32_t aoff0 = (uint32_t)((wm * 32 + mrow) * LDT + kcol) * 4u;
    uint32_t aoff1 = (uint32_t)((wm * 32 + 16 + mrow) * LDT + kcol) * 4u;
    uint32_t bb1[2], bb2[2];
    #pragma unroll
    for (int p = 0; p < 2; ++p) {
        bb1[p] = smb + (uint32_t)(SLOT     + (wn * 32 + p * 16 + mrow) * LDT + kcol) * 4u;
        bb2[p] = smb + (uint32_t)(2 * SLOT + (wn * 32 + p * 16 + mrow) * LDT + kcol) * 4u;
    }

    float4 gg  = *(const float4*)(lng + cc);
    float4 bbv = *(const float4*)(lnb + cc);

    for (int t = blockIdx.x; t < TILES_NODE; t += gridDim.x) {
        size_t row0 = (size_t)t * 128;
        __syncthreads();
        prefetch_A(sm, g_bred, row0, (size_t)M_NODES, tid);
        cpa_commit();
        cpa_wait0();
        __syncthreads();

        float c[2][4][4];
        zero_c(c);
        tile_gemm(smb + aoff0, smb + aoff1, bb1, c);

        __syncthreads();                       // all warps done reading bred tile
        prefetch_A(sm, tgt, row0, (size_t)M_NODES, tid);
        cpa_commit();
        cpa_wait0();
        __syncthreads();

        tile_gemm(smb + aoff0, smb + aoff1, bb2, c);

        #pragma unroll 1
        for (int p = 0; p < 4; ++p) {
            __syncthreads();
            stage_pass(Csh, c, p, wm, wn, lr, lc);
            __syncthreads();
            #pragma unroll
            for (int rr = 0; rr < 2; ++rr) {
                int rl = wid * 2 + rr;
                int r = p * 32 + rl;
                size_t gr = row0 + (size_t)r;
                if (gr >= (size_t)M_NODES) continue;
                float4 v = *(const float4*)(Csh + rl * LDT + cc);
                float x0 = silu_f(v.x);
                float x1 = silu_f(v.y);
                float x2 = silu_f(v.z);
                float x3 = silu_f(v.w);
                float s = x0 + x1 + x2 + x3;
                float q = x0 * x0 + x1 * x1 + x2 * x2 + x3 * x3;
                #pragma unroll
                for (int o = 16; o > 0; o >>= 1) {
                    s += __shfl_xor_sync(0xffffffffu, s, o);
                    q += __shfl_xor_sync(0xffffffffu, q, o);
                }
                float mean = s * (1.f / ND);
                float var  = q * (1.f / ND) - mean * mean;
                float rstd = rsqrtf(var + 1e-5f);
                float y0 = (x0 - mean) * rstd * gg.x + bbv.x;
                float y1 = (x1 - mean) * rstd * gg.y + bbv.y;
                float y2 = (x2 - mean) * rstd * gg.z + bbv.z;
                float y3 = (x3 - mean) * rstd * gg.w + bbv.w;
                float4 av = *(const float4*)(sm + r * LDT + cc);   // exact fp32 tgt
                *(float4*)(out2 + gr * ND + cc) =
                    make_float4(av.x + y0, av.y + y1, av.z + y2, av.w + y3);
            }
        }
    }
}

// ---------------------------------------------------------------- launch
extern "C" void kernel_launch(void* const* d_in, const int* in_sizes, int n_in,
                              void* d_out, int out_size) {
    const float* bond = (const float*)d_in[0];
    const float* src  = (const float*)d_in[1];
    const float* tgt  = (const float*)d_in[2];
    const float* Ws2e = (const float*)d_in[3];
    const float* Wt2e = (const float*)d_in[4];
    const float* We2e = (const float*)d_in[5];
    const float* ln1g = (const float*)d_in[6];
    const float* ln1b = (const float*)d_in[7];
    const float* We2t = (const float*)d_in[8];
    const float* Wt2t = (const float*)d_in[9];
    const float* ln2g = (const float*)d_in[10];
    const float* ln2b = (const float*)d_in[11];
    const float* coef = (const float*)d_in[12];
    const int* so = (const int*)d_in[13];
    const int* to = (const int*)d_in[14];
    const int* eo = (const int*)d_in[15];

    float* out0 = (float*)d_out;                     // [B,E,D]
    float* out1 = out0 + (size_t)NB * NE * ND;       // [B,NS,D]
    float* out2 = out1 + (size_t)NB * NS_N * ND;     // [B,NT,D]

    cudaFuncSetAttribute(proj_kernel, cudaFuncAttributeMaxDynamicSharedMemorySize, SMEM_BYTES);
    cudaFuncSetAttribute(edge_kernel, cudaFuncAttributeMaxDynamicSharedMemorySize, SMEM_BYTES);
    cudaFuncSetAttribute(tgt_fused,   cudaFuncAttributeMaxDynamicSharedMemorySize, SMEM_BYTES);

    // P_s = src@Ws2e (+ out1=src), P_t = tgt@Wt2e — one full wave
    proj_kernel<<<dim3(74, 2), NTHR, SMEM_BYTES>>>(src, tgt, Ws2e, Wt2e, out1);
    // edge block: out0 = bond + LN(silu(bond@We2e + gathers)), g_dbond
    edge_kernel<<<148, NTHR, SMEM_BYTES>>>(bond, We2e, ln1g, ln1b, so, to, out0);
    // bond -> node weighted mean
    gather_kernel<<<NB * NT_N, 128>>>(eo, coef);
    // out2 = tgt + LN(silu(bred@We2t + tgt@Wt2t))
    tgt_fused<<<148, NTHR, SMEM_BYTES>>>(tgt, We2t, Wt2t, ln2g, ln2b, out2);
}

// round 16
// speedup vs baseline: 1.6367x; 1.0875x over previous
#include <cuda_runtime.h>
#include <cuda_fp16.h>
#include <cstdint>
#include <cstddef>

// ---------------------------------------------------------------- constants
#define NB   4
#define NS_N 10000
#define NT_N 10000
#define NE   160000
#define NK   16
#define ND   128
#define M_NODES 40000
#define TILES_NODE 313
#define TILES_EDGE 5000
#define TILES_PER_BATCH 1250

#define NTHR 512
#define LDT 132     // fp32 tile stride (floats)
#define LDH 136     // fp16 tile stride (halves)

// edge/proj SMEM layout (float offsets):
//   F0=0, F1=16896 (fp32 A double buffer), A16=33792 (8704 fl), BT=42496 (8704 fl), C=51200 (4224 fl)
#define EP_F1   16896
#define EP_A16  33792
#define EP_BT   42496
#define EP_C    51200
#define SMEM_FLOATS 55424
#define SMEM_BYTES (SMEM_FLOATS * 4)     // 221696

// tgt_fused layout: F0=0, A16=16896, BT1=25600, BT2=34304, C=43008
#define TG_A16  16896
#define TG_BT1  25600
#define TG_BT2  34304
#define TG_C    43008

// ---------------------------------------------------------------- scratch
__device__ float g_Ps[(size_t)NB * NS_N * ND];
__device__ float g_Pt[(size_t)NB * NT_N * ND];
__device__ float g_dbond[(size_t)NB * NE * ND];
__device__ float g_bred[(size_t)NB * NT_N * ND];

// ---------------------------------------------------------------- helpers
__device__ __forceinline__ unsigned pk16(float lo, float hi) {
    unsigned r;
    asm("cvt.rn.f16x2.f32 %0, %1, %2;" : "=r"(r) : "f"(hi), "f"(lo));
    return r;
}
__device__ __forceinline__ void mma16(float c[4], const unsigned a[4], unsigned b0, unsigned b1) {
    asm volatile(
        "mma.sync.aligned.m16n8k16.row.col.f32.f16.f16.f32 "
        "{%0,%1,%2,%3},{%4,%5,%6,%7},{%8,%9},{%0,%1,%2,%3};"
        : "+f"(c[0]), "+f"(c[1]), "+f"(c[2]), "+f"(c[3])
        : "r"(a[0]), "r"(a[1]), "r"(a[2]), "r"(a[3]), "r"(b0), "r"(b1));
}
__device__ __forceinline__ void ldsm4(unsigned r[4], uint32_t addr) {
    asm volatile("ldmatrix.sync.aligned.m8n8.x4.shared.b16 {%0,%1,%2,%3}, [%4];"
                 : "=r"(r[0]), "=r"(r[1]), "=r"(r[2]), "=r"(r[3]) : "r"(addr));
}
__device__ __forceinline__ float silu_f(float x) { return x / (1.f + __expf(-x)); }

__device__ __forceinline__ void prefetch_A(float* Adst, const float* __restrict__ Ag,
                                           size_t row0, size_t M, int tid) {
    uint32_t dst0 = (uint32_t)__cvta_generic_to_shared(Adst);
    #pragma unroll
    for (int i = 0; i < 8; ++i) {
        int t = tid + i * NTHR;
        int r = t >> 5, c4 = (t & 31) << 2;
        size_t rr = row0 + (size_t)r;
        if (rr >= M) rr = M - 1;
        uint32_t d = dst0 + (uint32_t)(r * LDT + c4) * 4u;
        const float* s = Ag + rr * ND + c4;
        asm volatile("cp.async.cg.shared.global [%0], [%1], 16;" :: "r"(d), "l"(s));
    }
}
__device__ __forceinline__ void cpa_commit() { asm volatile("cp.async.commit_group;" ::: "memory"); }
__device__ __forceinline__ void cpa_wait0()  { asm volatile("cp.async.wait_group 0;"  ::: "memory"); }

// convert fp32 SMEM tile -> fp16 SMEM tile (rn)
__device__ __forceinline__ void conv_A16(const float* F, void* A16, int tid) {
    #pragma unroll
    for (int i = 0; i < 8; ++i) {
        int t = tid + i * NTHR;
        int r = t >> 5, c4 = (t & 31) << 2;
        float4 v = *(const float4*)(F + r * LDT + c4);
        uint2 o;
        o.x = pk16(v.x, v.y);
        o.y = pk16(v.z, v.w);
        *(uint2*)((char*)A16 + ((size_t)r * LDH + c4) * 2) = o;
    }
}

// BT16[n][k] = half(W[k][n])   (once per kernel)
__device__ __forceinline__ void stage_BT16(void* BTp, const float* __restrict__ W, int tid) {
    __half* p = (__half*)BTp;
    #pragma unroll
    for (int i = 0; i < 8; ++i) {
        int t = tid + i * NTHR;
        int k = t >> 5, c4 = (t & 31) << 2;
        float4 v = *(const float4*)(W + k * ND + c4);
        p[(c4 + 0) * LDH + k] = __float2half_rn(v.x);
        p[(c4 + 1) * LDH + k] = __float2half_rn(v.y);
        p[(c4 + 2) * LDH + k] = __float2half_rn(v.z);
        p[(c4 + 3) * LDH + k] = __float2half_rn(v.w);
    }
}

// 128x128x128 fp16 tile GEMM: 16 warps (4m x 4n), warp tile 32x32, dbl-buffered frags
// a0/a1: per-lane ldsm addrs for m-halves at k-chunk 0; b0/b1: khalf 0/1
__device__ __forceinline__ void tile_gemm16(uint32_t a0, uint32_t a1, uint32_t b0, uint32_t b1,
                                            float c[2][4][4]) {
    unsigned A[2][2][4], B[2][2][4];
#define LK(s, kb) do { \
    ldsm4(A[s][0], a0 + (kb)); \
    ldsm4(A[s][1], a1 + (kb)); \
    ldsm4(B[s][0], b0 + (kb)); \
    ldsm4(B[s][1], b1 + (kb)); } while (0)
    LK(0, 0);
    #pragma unroll
    for (int kk = 0; kk < 8; ++kk) {
        int s = kk & 1;
        if (kk < 7) {
            uint32_t kb = (uint32_t)(kk + 1) * 32u;   // 16 halves = 32 B per k-step
            if (s == 0) LK(1, kb); else LK(0, kb);
        }
        #pragma unroll
        for (int i = 0; i < 2; ++i)
            #pragma unroll
            for (int j = 0; j < 4; ++j)
                mma16(c[i][j], A[s][i], B[s][0][j], B[s][1][j]);
    }
#undef LK
}

__device__ __forceinline__ void zero_c(float c[2][4][4]) {
    #pragma unroll
    for (int i = 0; i < 2; ++i)
        #pragma unroll
        for (int j = 0; j < 4; ++j)
            c[i][j][0] = c[i][j][1] = c[i][j][2] = c[i][j][3] = 0.f;
}

// stage one 32-row pass of C (warps with wm==p write); same frag layout as fp16 mma C
__device__ __forceinline__ void stage_pass(float* Csh, float c[2][4][4], int p,
                                           int wm, int wn, int lr, int lc) {
    if (wm == p) {
        #pragma unroll
        for (int i = 0; i < 2; ++i)
            #pragma unroll
            for (int j = 0; j < 4; ++j) {
                int rl = i * 16 + lr;
                int col = wn * 32 + j * 8 + lc * 2;
                *(float2*)(Csh + rl * LDT + col)       = make_float2(c[i][j][0], c[i][j][1]);
                *(float2*)(Csh + (rl + 8) * LDT + col) = make_float2(c[i][j][2], c[i][j][3]);
            }
    }
}

// ---------------------------------------------------------------- K1: projections
// y==0: g_Ps = src @ Ws2e, out1 = src ; y==1: g_Pt = tgt @ Wt2e
__global__ __launch_bounds__(NTHR) void proj_kernel(const float* __restrict__ src,
                                                    const float* __restrict__ tgt,
                                                    const float* __restrict__ Ws,
                                                    const float* __restrict__ Wt,
                                                    float* __restrict__ out1) {
    extern __shared__ float sm[];
    float* Csh = sm + EP_C;
    int tid = threadIdx.x, lane = tid & 31, wid = tid >> 5;
    int wm = wid & 3, wn = wid >> 2;
    int lr = lane >> 2, lc = lane & 3;
    int cc = lane << 2;

    const float* Ag = blockIdx.y ? tgt : src;
    const float* Wg = blockIdx.y ? Wt : Ws;
    float* O = blockIdx.y ? g_Pt : g_Ps;
    float* copy_out = blockIdx.y ? nullptr : out1;

    stage_BT16(sm + EP_BT, Wg, tid);

    uint32_t smb = (uint32_t)__cvta_generic_to_shared(sm);
    uint32_t a16b = smb + EP_A16 * 4u;
    int l15 = lane & 15, lk = (lane >> 4) * 8;
    uint32_t aoff0 = a16b + (uint32_t)(((wm * 32 + l15) * LDH + lk) * 2);
    uint32_t aoff1 = aoff0 + (uint32_t)(16 * LDH * 2);
    uint32_t boff0 = smb + EP_BT * 4u + (uint32_t)(((wn * 32 + lane) * LDH) * 2);
    uint32_t boff1 = boff0 + 16u;

    prefetch_A(sm, Ag, (size_t)blockIdx.x * 128, (size_t)M_NODES, tid);
    cpa_commit();

    int buf = 0;
    for (int t = blockIdx.x; t < TILES_NODE; t += gridDim.x, buf ^= 1) {
        cpa_wait0();
        __syncthreads();
        int tn = t + gridDim.x;
        if (tn < TILES_NODE)
            prefetch_A(sm + (buf ^ 1) * EP_F1, Ag, (size_t)tn * 128, (size_t)M_NODES, tid);
        cpa_commit();

        const float* Ash = sm + buf * EP_F1;
        conv_A16(Ash, sm + EP_A16, tid);
        __syncthreads();

        size_t row0 = (size_t)t * 128;
        float c[2][4][4];
        zero_c(c);
        tile_gemm16(aoff0, aoff1, boff0, boff1, c);

        if (copy_out) {
            #pragma unroll
            for (int rr = 0; rr < 8; ++rr) {
                int r = wid * 8 + rr;
                size_t gr = row0 + (size_t)r;
                if (gr < (size_t)M_NODES)
                    *(float4*)(copy_out + gr * ND + cc) = *(const float4*)(Ash + r * LDT + cc);
            }
        }

        #pragma unroll 1
        for (int p = 0; p < 4; ++p) {
            __syncthreads();
            stage_pass(Csh, c, p, wm, wn, lr, lc);
            __syncthreads();
            #pragma unroll
            for (int rr = 0; rr < 2; ++rr) {
                int rl = wid * 2 + rr;
                size_t gr = row0 + (size_t)(p * 32 + rl);
                if (gr < (size_t)M_NODES)
                    *(float4*)(O + gr * ND + cc) = *(const float4*)(Csh + rl * LDT + cc);
            }
        }
    }
}

// ---------------------------------------------------------------- K2: edge block
__global__ __launch_bounds__(NTHR) void edge_kernel(const float* __restrict__ bond,
                                                    const float* __restrict__ We2e,
                                                    const float* __restrict__ lng,
                                                    const float* __restrict__ lnb,
                                                    const int* __restrict__ so,
                                                    const int* __restrict__ to,
                                                    float* __restrict__ out0) {
    extern __shared__ float sm[];
    float* Csh = sm + EP_C;
    int tid = threadIdx.x, lane = tid & 31, wid = tid >> 5;
    int wm = wid & 3, wn = wid >> 2;
    int lr = lane >> 2, lc = lane & 3;
    int cc = lane << 2;

    stage_BT16(sm + EP_BT, We2e, tid);

    uint32_t smb = (uint32_t)__cvta_generic_to_shared(sm);
    uint32_t a16b = smb + EP_A16 * 4u;
    int l15 = lane & 15, lk = (lane >> 4) * 8;
    uint32_t aoff0 = a16b + (uint32_t)(((wm * 32 + l15) * LDH + lk) * 2);
    uint32_t aoff1 = aoff0 + (uint32_t)(16 * LDH * 2);
    uint32_t boff0 = smb + EP_BT * 4u + (uint32_t)(((wn * 32 + lane) * LDH) * 2);
    uint32_t boff1 = boff0 + 16u;

    float4 gg  = *(const float4*)(lng + cc);
    float4 bbv = *(const float4*)(lnb + cc);

    prefetch_A(sm, bond, (size_t)blockIdx.x * 128, (size_t)NB * NE, tid);
    cpa_commit();

    int buf = 0;
    for (int t = blockIdx.x; t < TILES_EDGE; t += gridDim.x, buf ^= 1) {
        cpa_wait0();
        __syncthreads();
        int tn = t + gridDim.x;
        if (tn < TILES_EDGE)
            prefetch_A(sm + (buf ^ 1) * EP_F1, bond, (size_t)tn * 128, (size_t)NB * NE, tid);
        cpa_commit();

        const float* Ash = sm + buf * EP_F1;
        conv_A16(Ash, sm + EP_A16, tid);
        __syncthreads();

        size_t row0 = (size_t)t * 128;
        float c[2][4][4];
        zero_c(c);
        tile_gemm16(aoff0, aoff1, boff0, boff1, c);

        int b = t / TILES_PER_BATCH;
        int el0 = (t - b * TILES_PER_BATCH) * 128;
        const float* PsB = g_Ps + (size_t)b * NS_N * ND;
        const float* PtB = g_Pt + (size_t)b * NT_N * ND;

        #pragma unroll 1
        for (int p = 0; p < 4; ++p) {
            __syncthreads();
            stage_pass(Csh, c, p, wm, wn, lr, lc);
            __syncthreads();
            #pragma unroll
            for (int rr = 0; rr < 2; ++rr) {
                int rl = wid * 2 + rr;
                int r = p * 32 + rl;
                int el = el0 + r;
                int si = __ldg(so + el);
                int ti = __ldg(to + el);
                float4 v  = *(const float4*)(Csh + rl * LDT + cc);
                float4 ps = *(const float4*)(PsB + (size_t)si * ND + cc);
                float4 pt = *(const float4*)(PtB + (size_t)ti * ND + cc);
                float x0 = silu_f(v.x + ps.x + pt.x);
                float x1 = silu_f(v.y + ps.y + pt.y);
                float x2 = silu_f(v.z + ps.z + pt.z);
                float x3 = silu_f(v.w + ps.w + pt.w);
                float s = x0 + x1 + x2 + x3;
                float q = x0 * x0 + x1 * x1 + x2 * x2 + x3 * x3;
                #pragma unroll
                for (int o = 16; o > 0; o >>= 1) {
                    s += __shfl_xor_sync(0xffffffffu, s, o);
                    q += __shfl_xor_sync(0xffffffffu, q, o);
                }
                float mean = s * (1.f / ND);
                float var  = q * (1.f / ND) - mean * mean;
                float rstd = rsqrtf(var + 1e-5f);
                float y0 = (x0 - mean) * rstd * gg.x + bbv.x;
                float y1 = (x1 - mean) * rstd * gg.y + bbv.y;
                float y2 = (x2 - mean) * rstd * gg.z + bbv.z;
                float y3 = (x3 - mean) * rstd * gg.w + bbv.w;
                size_t off = (row0 + (size_t)r) * ND + cc;
                float4 av = *(const float4*)(Ash + r * LDT + cc);   // exact fp32 bond
                *(float4*)(g_dbond + off) = make_float4(y0, y1, y2, y3);
                *(float4*)(out0 + off) = make_float4(av.x + y0, av.y + y1, av.z + y2, av.w + y3);
            }
        }
    }
}

// ---------------------------------------------------------------- K3: gather
__global__ __launch_bounds__(128) void gather_kernel(const int* __restrict__ edge_order,
                                                     const float* __restrict__ coef) {
    int bn = blockIdx.x;                 // 0 .. B*NT-1
    int b = bn / NT_N, nt = bn - b * NT_N;
    __shared__ int   eo[NK];
    __shared__ float cf[NK];
    if (threadIdx.x < NK) {
        eo[threadIdx.x] = edge_order[nt * NK + threadIdx.x];
        cf[threadIdx.x] = coef[nt * NK + threadIdx.x];
    }
    __syncthreads();
    int d = threadIdx.x;
    const float* base = g_dbond + (size_t)b * NE * ND;
    float acc = 0.f;
    #pragma unroll
    for (int k = 0; k < NK; ++k)
        acc += cf[k] * __ldg(base + (size_t)eo[k] * ND + d);
    g_bred[(size_t)bn * ND + d] = acc * (1.f / NK);
}

// ---------------------------------------------------------------- K4: fused tgt update
// out2 = tgt + LN(silu(bred@We2t + tgt@Wt2t))
__global__ __launch_bounds__(NTHR) void tgt_fused(const float* __restrict__ tgt,
                                                  const float* __restrict__ We2t,
                                                  const float* __restrict__ Wt2t,
                                                  const float* __restrict__ lng,
                                                  const float* __restrict__ lnb,
                                                  float* __restrict__ out2) {
    extern __shared__ float sm[];
    float* Csh = sm + TG_C;
    int tid = threadIdx.x, lane = tid & 31, wid = tid >> 5;
    int wm = wid & 3, wn = wid >> 2;
    int lr = lane >> 2, lc = lane & 3;
    int cc = lane << 2;

    stage_BT16(sm + TG_BT1, We2t, tid);
    stage_BT16(sm + TG_BT2, Wt2t, tid);
    __syncthreads();

    uint32_t smb = (uint32_t)__cvta_generic_to_shared(sm);
    uint32_t a16b = smb + TG_A16 * 4u;
    int l15 = lane & 15, lk = (lane >> 4) * 8;
    uint32_t aoff0 = a16b + (uint32_t)(((wm * 32 + l15) * LDH + lk) * 2);
    uint32_t aoff1 = aoff0 + (uint32_t)(16 * LDH * 2);
    uint32_t b1off0 = smb + TG_BT1 * 4u + (uint32_t)(((wn * 32 + lane) * LDH) * 2);
    uint32_t b1off1 = b1off0 + 16u;
    uint32_t b2off0 = smb + TG_BT2 * 4u + (uint32_t)(((wn * 32 + lane) * LDH) * 2);
    uint32_t b2off1 = b2off0 + 16u;

    float4 gg  = *(const float4*)(lng + cc);
    float4 bbv = *(const float4*)(lnb + cc);

    for (int t = blockIdx.x; t < TILES_NODE; t += gridDim.x) {
        size_t row0 = (size_t)t * 128;

        prefetch_A(sm, g_bred, row0, (size_t)M_NODES, tid);
        cpa_commit();
        cpa_wait0();
        __syncthreads();
        conv_A16(sm, sm + TG_A16, tid);
        __syncthreads();

        // tgt tile load overlaps GEMM1 (GEMM reads the fp16 copy)
        prefetch_A(sm, tgt, row0, (size_t)M_NODES, tid);
        cpa_commit();

        float c[2][4][4];
        zero_c(c);
        tile_gemm16(aoff0, aoff1, b1off0, b1off1, c);

        cpa_wait0();
        __syncthreads();
        conv_A16(sm, sm + TG_A16, tid);
        __syncthreads();

        tile_gemm16(aoff0, aoff1, b2off0, b2off1, c);

        #pragma unroll 1
        for (int p = 0; p < 4; ++p) {
            __syncthreads();
            stage_pass(Csh, c, p, wm, wn, lr, lc);
            __syncthreads();
            #pragma unroll
            for (int rr = 0; rr < 2; ++rr) {
                int rl = wid * 2 + rr;
                int r = p * 32 + rl;
                size_t gr = row0 + (size_t)r;
                if (gr >= (size_t)M_NODES) continue;
                float4 v = *(const float4*)(Csh + rl * LDT + cc);
                float x0 = silu_f(v.x);
                float x1 = silu_f(v.y);
                float x2 = silu_f(v.z);
                float x3 = silu_f(v.w);
                float s = x0 + x1 + x2 + x3;
                float q = x0 * x0 + x1 * x1 + x2 * x2 + x3 * x3;
                #pragma unroll
                for (int o = 16; o > 0; o >>= 1) {
                    s += __shfl_xor_sync(0xffffffffu, s, o);
                    q += __shfl_xor_sync(0xffffffffu, q, o);
                }
                float mean = s * (1.f / ND);
                float var  = q * (1.f / ND) - mean * mean;
                float rstd = rsqrtf(var + 1e-5f);
                float y0 = (x0 - mean) * rstd * gg.x + bbv.x;
                float y1 = (x1 - mean) * rstd * gg.y + bbv.y;
                float y2 = (x2 - mean) * rstd * gg.z + bbv.z;
                float y3 = (x3 - mean) * rstd * gg.w + bbv.w;
                float4 av = *(const float4*)(sm + r * LDT + cc);   // exact fp32 tgt
                *(float4*)(out2 + gr * ND + cc) =
                    make_float4(av.x + y0, av.y + y1, av.z + y2, av.w + y3);
            }
        }
        __syncthreads();   // epilogue reads of slot0 done before next prefetch
    }
}

// ---------------------------------------------------------------- launch
extern "C" void kernel_launch(void* const* d_in, const int* in_sizes, int n_in,
                              void* d_out, int out_size) {
    const float* bond = (const float*)d_in[0];
    const float* src  = (const float*)d_in[1];
    const float* tgt  = (const float*)d_in[2];
    const float* Ws2e = (const float*)d_in[3];
    const float* Wt2e = (const float*)d_in[4];
    const float* We2e = (const float*)d_in[5];
    const float* ln1g = (const float*)d_in[6];
    const float* ln1b = (const float*)d_in[7];
    const float* We2t = (const float*)d_in[8];
    const float* Wt2t = (const float*)d_in[9];
    const float* ln2g = (const float*)d_in[10];
    const float* ln2b = (const float*)d_in[11];
    const float* coef = (const float*)d_in[12];
    const int* so = (const int*)d_in[13];
    const int* to = (const int*)d_in[14];
    const int* eo = (const int*)d_in[15];

    float* out0 = (float*)d_out;                     // [B,E,D]
    float* out1 = out0 + (size_t)NB * NE * ND;       // [B,NS,D]
    float* out2 = out1 + (size_t)NB * NS_N * ND;     // [B,NT,D]

    cudaFuncSetAttribute(proj_kernel, cudaFuncAttributeMaxDynamicSharedMemorySize, SMEM_BYTES);
    cudaFuncSetAttribute(edge_kernel, cudaFuncAttributeMaxDynamicSharedMemorySize, SMEM_BYTES);
    cudaFuncSetAttribute(tgt_fused,   cudaFuncAttributeMaxDynamicSharedMemorySize, SMEM_BYTES);

    proj_kernel<<<dim3(74, 2), NTHR, SMEM_BYTES>>>(src, tgt, Ws2e, Wt2e, out1);
    edge_kernel<<<148, NTHR, SMEM_BYTES>>>(bond, We2e, ln1g, ln1b, so, to, out0);
    gather_kernel<<<NB * NT_N, 128>>>(eo, coef);
    tgt_fused<<<148, NTHR, SMEM_BYTES>>>(tgt, We2t, Wt2t, ln2g, ln2b, out2);
}